// round 12
// baseline (speedup 1.0000x reference)
#include <cuda_runtime.h>
#include <cuda_fp16.h>

#define NN 50000
#define EE 400000
#define ETOT 450000            // EE + NN self loops
#define NB 196                 // ceil(NN/256)
#define G1B 782                // ceil(NN/64)
#define FULLMASK 0xffffffffu

// ---------------- static scratch (no allocations allowed) ----------------
__device__ uint4              g_h1h[NN * 32];   // layer1 features fp16 [N,4,64]
__device__ float4             g_asrc1[NN];      // [N,4]
__device__ float4             g_adst1[NN];      // [N,4]
__device__ float              g_h1out[NN * 64]; // layer1 output after mean+bias+ELU
__device__ unsigned           g_h2h[NN * 32];   // layer2 features fp16 [N,64], 32 half2/node
__device__ float              g_asrc2[NN];
__device__ float              g_adst2[NN];
__device__ int                g_counts[NN];     // starts zero; re-zeroed by k_scan each launch
__device__ int                g_offsets[NN + 1];
__device__ int                g_cursor[NN];
__device__ int                g_csr_src[ETOT];
__device__ unsigned long long g_desc[NB];       // lookback: status<<32 | value (zeroed by gemm1_hist)

__device__ __forceinline__ float lrelu(float v) { return v > 0.f ? v : 0.2f * v; }
__device__ __forceinline__ float elu(float v)   { return v > 0.f ? v : expm1f(v); }

__device__ __forceinline__ int edge_val(const void* ei, int idx, bool is64) {
    if (is64) return (int)((const long long*)ei)[idx];
    return ((const int*)ei)[idx];
}

__device__ __forceinline__ float pick4(float4 v, int s) {
    return (s == 0) ? v.x : (s == 1) ? v.y : (s == 2) ? v.z : v.w;
}

// Per-block dtype probe: int64 non-negative values < 2^31 have zero odd words.
// Call with all threads; returns via shared flag. Needs two __syncthreads.
__device__ __forceinline__ bool probe_is64(const unsigned* ei32, int t, int* s_flag) {
    if (t == 0) *s_flag = 0;
    __syncthreads();
    if (t < 64) {
        unsigned a = __ldg(&ei32[2 * t + 1]);
        if (a) atomicOr(s_flag, 1);
    }
    __syncthreads();
    return *s_flag == 0;
}

// ---------------- fused: layer1 GEMM (+att coeffs, per-block u) + dst histogram ----------------
__global__ void k_gemm1_hist(const float* __restrict__ x, const float* __restrict__ W1,
                             const float* __restrict__ as1, const float* __restrict__ ad1,
                             const void* __restrict__ ei) {
    int t = threadIdx.x;
    int b = blockIdx.x;
    if (b < G1B) {
        __shared__ float Ws[4096];
        __shared__ float xs[1024];
        __shared__ float s_u[128];           // usrc1[64] (k*4+h), udst1[64]
        int base = b * 64;
        for (int i = t; i < 4096; i += 256) Ws[i] = W1[i];
        for (int i = t; i < 1024; i += 256) {
            int gi = base * 16 + i;
            xs[i] = (gi < NN * 16) ? x[gi] : 0.f;
        }
        __syncthreads();
        // folded attention vectors from smem W1 (concurrent with the tile compute)
        if (t < 64) {
            int k = t >> 2, h = t & 3;
            float s = 0.f, d = 0.f;
#pragma unroll 16
            for (int c = 0; c < 64; c++) {
                float w = Ws[k * 256 + h * 64 + c];
                s += w * __ldg(&as1[h * 64 + c]);
                d += w * __ldg(&ad1[h * 64 + c]);
            }
            s_u[t]      = s;
            s_u[64 + t] = d;
        }
        int ct = t & 31, nt = t >> 5;
        float acc[8][8];
#pragma unroll
        for (int i = 0; i < 8; i++)
#pragma unroll
            for (int j = 0; j < 8; j++) acc[i][j] = 0.f;
#pragma unroll
        for (int k = 0; k < 16; k++) {
            float4 wa = *(const float4*)&Ws[k * 256 + ct * 8];
            float4 wb = *(const float4*)&Ws[k * 256 + ct * 8 + 4];
#pragma unroll
            for (int i = 0; i < 8; i++) {
                float xv = xs[(nt * 8 + i) * 16 + k];
                acc[i][0] += xv * wa.x; acc[i][1] += xv * wa.y;
                acc[i][2] += xv * wa.z; acc[i][3] += xv * wa.w;
                acc[i][4] += xv * wb.x; acc[i][5] += xv * wb.y;
                acc[i][6] += xv * wb.z; acc[i][7] += xv * wb.w;
            }
        }
#pragma unroll
        for (int i = 0; i < 8; i++) {
            int node = base + nt * 8 + i;
            if (node < NN) {
                __half2 h0 = __floats2half2_rn(acc[i][0], acc[i][1]);
                __half2 h1 = __floats2half2_rn(acc[i][2], acc[i][3]);
                __half2 h2 = __floats2half2_rn(acc[i][4], acc[i][5]);
                __half2 h3 = __floats2half2_rn(acc[i][6], acc[i][7]);
                uint4 u;
                u.x = *(unsigned*)&h0; u.y = *(unsigned*)&h1;
                u.z = *(unsigned*)&h2; u.w = *(unsigned*)&h3;
                g_h1h[node * 32 + ct] = u;
            }
        }
        __syncthreads();                      // s_u ready for all threads
        {
            int nl = t >> 2, h = t & 3;
            int node = base + nl;
            if (node < NN) {
                float s = 0.f, d = 0.f;
#pragma unroll
                for (int k = 0; k < 16; k++) {
                    float xv = xs[nl * 16 + k];
                    s += xv * s_u[k * 4 + h];
                    d += xv * s_u[64 + k * 4 + h];
                }
                ((float*)g_asrc1)[node * 4 + h] = s;
                ((float*)g_adst1)[node * 4 + h] = d;
            }
        }
    } else {
        __shared__ int s_flag;
        bool is64 = probe_is64((const unsigned*)ei, t, &s_flag);
        if (b == G1B && t < NB) g_desc[t] = 0ULL;    // reset lookback descriptors for k_scan
        int e = (b - G1B) * 256 + t;
        if (e < ETOT) {
            int dst = (e < EE) ? edge_val(ei, EE + e, is64) : (e - EE);
            atomicAdd(&g_counts[dst], 1);
        }
    }
}

// ---------------- single-pass scan with decoupled lookback (aggregates published) ----------------
__global__ void k_scan() {
    __shared__ int wsum[8];
    __shared__ int s_prefix;
    int t = threadIdx.x;
    int b = blockIdx.x;
    int i = b * 256 + t;
    int c = (i < NN) ? g_counts[i] : 0;
    if (i < NN) g_counts[i] = 0;             // re-zero for next graph replay
    int v = c;
#pragma unroll
    for (int o = 1; o < 32; o <<= 1) {
        int y = __shfl_up_sync(FULLMASK, v, o);
        if ((t & 31) >= o) v += y;
    }
    if ((t & 31) == 31) wsum[t >> 5] = v;
    __syncthreads();
    if (t < 8) {
        int w = wsum[t];
#pragma unroll
        for (int o = 1; o < 8; o <<= 1) {
            int y = __shfl_up_sync(0x000000ffu, w, o);
            if (t >= o) w += y;
        }
        wsum[t] = w;
    }
    __syncthreads();
    int incl = v + ((t >= 32) ? wsum[(t >> 5) - 1] : 0);
    int total = wsum[7];

    if (t < 32) {
        int lane = t;
        // publish aggregate (status 1) immediately
        if (lane == 0)
            atomicExch(&g_desc[b], (1ULL << 32) | (unsigned long long)(unsigned)total);
        int prefix = 0;
        if (b > 0) {
            int idx = b - 1;
            while (true) {
                int ii = idx - lane;
                bool valid = ii >= 0;
                unsigned long long w = valid ? atomicAdd(&g_desc[ii], 0ULL) : 0ULL;
                int st = valid ? (int)(w >> 32) : 1;
                if (__ballot_sync(FULLMASK, valid && st == 0)) continue;   // not ready
                unsigned incm = __ballot_sync(FULLMASK, valid && st == 2);
                int add;
                if (incm) {
                    int j = __ffs(incm) - 1;           // closest inclusive
                    add = (lane <= j) ? (int)(w & 0xffffffffULL) : 0;
                } else {
                    if (idx < 32) continue;            // window reaches block 0: wait for its inclusive
                    add = valid ? (int)(w & 0xffffffffULL) : 0;
                }
#pragma unroll
                for (int o = 16; o; o >>= 1) add += __shfl_xor_sync(FULLMASK, add, o);
                prefix += add;
                if (incm) break;
                idx -= 32;
            }
        }
        if (lane == 0) {
            atomicExch(&g_desc[b], (2ULL << 32) | (unsigned long long)(unsigned)(prefix + total));
            s_prefix = prefix;
        }
    }
    __syncthreads();
    if (i < NN) {
        int off = incl - c + s_prefix;
        g_offsets[i] = off;
        g_cursor[i]  = off;
    }
    if (b == 0 && t == 0) g_offsets[NN] = ETOT;
}

// ---------------- scatter edges to CSR (src only), 2 edges/thread ----------------
__global__ void k_scatter(const void* __restrict__ ei) {
    __shared__ int s_flag;
    int t = threadIdx.x;
    bool is64 = probe_is64((const unsigned*)ei, t, &s_flag);
    int e0 = blockIdx.x * 512 + t;
#pragma unroll
    for (int k = 0; k < 2; k++) {
        int e = e0 + k * 256;
        if (e < ETOT) {
            int src, dst;
            if (e < EE) { src = edge_val(ei, e, is64); dst = edge_val(ei, EE + e, is64); }
            else        { src = e - EE; dst = e - EE; }
            int pos = atomicAdd(&g_cursor[dst], 1);
            g_csr_src[pos] = src;
        }
    }
}

// ---------------- layer1 aggregation: warp per node, batch-of-8 shared exp ----------------
__global__ void __launch_bounds__(256, 6) k_agg1(const float* __restrict__ b1) {
    int warp = (blockIdx.x * blockDim.x + threadIdx.x) >> 5;
    int l = threadIdx.x & 31;
    if (warp >= NN) return;
    int n = warp;
    int p0 = g_offsets[n], p1 = g_offsets[n + 1];
    int d = p1 - p0;
    int hsel = l >> 3;
    int el = l & 7;
    float adh = pick4(g_adst1[n], hsel);

    float acc[8] = {0,0,0,0,0,0,0,0};
    float denp = 0.f;                      // own-slot exp partial

    int base = 0;
    for (; base + 8 <= d; base += 8) {
        int s = g_csr_src[p0 + base + el];
        float ash = pick4(__ldg(&g_asrc1[s]), hsel);
        float ex = expf(lrelu(ash + adh));
        denp += ex;
#pragma unroll
        for (int j = 0; j < 8; j++) {
            int   src = __shfl_sync(FULLMASK, s,  hsel * 8 + j);
            float exh = __shfl_sync(FULLMASK, ex, hsel * 8 + j);
            uint4 u = g_h1h[src * 32 + l];
            __half2* hh = (__half2*)&u;
            float2 v0 = __half22float2(hh[0]);
            float2 v1 = __half22float2(hh[1]);
            float2 v2 = __half22float2(hh[2]);
            float2 v3 = __half22float2(hh[3]);
            acc[0] += exh * v0.x; acc[1] += exh * v0.y;
            acc[2] += exh * v1.x; acc[3] += exh * v1.y;
            acc[4] += exh * v2.x; acc[5] += exh * v2.y;
            acc[6] += exh * v3.x; acc[7] += exh * v3.y;
        }
    }
    if (base < d) {
        int jm = d - base;
        int s = 0; float ex = 0.f;
        if (el < jm) {
            s = g_csr_src[p0 + base + el];
            float ash = pick4(__ldg(&g_asrc1[s]), hsel);
            ex = expf(lrelu(ash + adh));
        }
        denp += ex;
        for (int j = 0; j < jm; j++) {
            int   src = __shfl_sync(FULLMASK, s,  hsel * 8 + j);
            float exh = __shfl_sync(FULLMASK, ex, hsel * 8 + j);
            uint4 u = g_h1h[src * 32 + l];
            __half2* hh = (__half2*)&u;
            float2 v0 = __half22float2(hh[0]);
            float2 v1 = __half22float2(hh[1]);
            float2 v2 = __half22float2(hh[2]);
            float2 v3 = __half22float2(hh[3]);
            acc[0] += exh * v0.x; acc[1] += exh * v0.y;
            acc[2] += exh * v1.x; acc[3] += exh * v1.y;
            acc[4] += exh * v2.x; acc[5] += exh * v2.y;
            acc[6] += exh * v3.x; acc[7] += exh * v3.y;
        }
    }

    float den = denp;
    den += __shfl_xor_sync(FULLMASK, den, 1);
    den += __shfl_xor_sync(FULLMASK, den, 2);
    den += __shfl_xor_sync(FULLMASK, den, 4);

    float inv = 0.25f / (den + 1e-16f);
    float r[8];
#pragma unroll
    for (int j = 0; j < 8; j++) {
        r[j] = acc[j] * inv;
        r[j] += __shfl_xor_sync(FULLMASK, r[j], 8);
        r[j] += __shfl_xor_sync(FULLMASK, r[j], 16);
    }
    if (l < 8) {
        float4 o0, o1;
        o0.x = elu(r[0] + b1[l * 8 + 0]);
        o0.y = elu(r[1] + b1[l * 8 + 1]);
        o0.z = elu(r[2] + b1[l * 8 + 2]);
        o0.w = elu(r[3] + b1[l * 8 + 3]);
        o1.x = elu(r[4] + b1[l * 8 + 4]);
        o1.y = elu(r[5] + b1[l * 8 + 5]);
        o1.z = elu(r[6] + b1[l * 8 + 6]);
        o1.w = elu(r[7] + b1[l * 8 + 7]);
        float4* op = (float4*)(g_h1out + n * 64) + l * 2;
        op[0] = o0;
        op[1] = o1;
    }
}

// ---------------- layer2 GEMM (per-block u, fp16 out) + att coeffs ----------------
__global__ void k_gemm2(const float* __restrict__ W2,
                        const float* __restrict__ as2, const float* __restrict__ ad2) {
    __shared__ float Ws[4096];
    __shared__ float xs[4096];
    __shared__ float s_u[128];              // usrc2[64], udst2[64]
    int t = threadIdx.x;
    int base = blockIdx.x * 64;
    for (int i = t; i < 4096; i += 256) {
        Ws[i] = W2[i];
        int gi = base * 64 + i;
        xs[i] = (gi < NN * 64) ? g_h1out[gi] : 0.f;
    }
    __syncthreads();
    if (t < 128) {
        int k = t & 63;
        const float* av = (t < 64) ? as2 : ad2;
        float s = 0.f;
#pragma unroll 16
        for (int c = 0; c < 64; c++) s += Ws[k * 64 + c] * __ldg(&av[c]);
        s_u[t] = s;
    }
    int ct = t & 15, nt = t >> 4;
    float acc[4][4];
#pragma unroll
    for (int i = 0; i < 4; i++)
#pragma unroll
        for (int j = 0; j < 4; j++) acc[i][j] = 0.f;
#pragma unroll 8
    for (int k = 0; k < 64; k++) {
        float4 w = *(const float4*)&Ws[k * 64 + ct * 4];
#pragma unroll
        for (int i = 0; i < 4; i++) {
            float xv = xs[(nt * 4 + i) * 64 + k];
            acc[i][0] += xv * w.x; acc[i][1] += xv * w.y;
            acc[i][2] += xv * w.z; acc[i][3] += xv * w.w;
        }
    }
#pragma unroll
    for (int i = 0; i < 4; i++) {
        int node = base + nt * 4 + i;
        if (node < NN) {
            __half2 h0 = __floats2half2_rn(acc[i][0], acc[i][1]);
            __half2 h1 = __floats2half2_rn(acc[i][2], acc[i][3]);
            uint2 o;
            o.x = *(unsigned*)&h0;
            o.y = *(unsigned*)&h1;
            *(uint2*)&g_h2h[node * 32 + ct * 2] = o;
        }
    }
    __syncthreads();                        // s_u ready
    if (t < 128) {
        int nl = t >> 1;
        bool isdst = t & 1;
        int node = base + nl;
        if (node < NN) {
            const float* u = s_u + (isdst ? 64 : 0);
            float a = 0.f;
#pragma unroll 16
            for (int k = 0; k < 64; k++) a += xs[nl * 64 + k] * u[k];
            if (isdst) g_adst2[node] = a; else g_asrc2[node] = a;
        }
    }
}

// ---------------- layer2 aggregation with inline exp, fp16 gathers ----------------
__global__ void k_agg2(const float* __restrict__ b2, float* __restrict__ out) {
    int warp = (blockIdx.x * blockDim.x + threadIdx.x) >> 5;
    int l = threadIdx.x & 31;
    if (warp >= NN) return;
    int n = warp;
    int p0 = g_offsets[n], p1 = g_offsets[n + 1];
    int d = p1 - p0;
    float adst2n = g_adst2[n];

    int   sa0 = 0,  sa1 = 0;
    float ea0 = 0.f, ea1 = 0.f;
    if (l < d) {
        sa0 = g_csr_src[p0 + l];
        ea0 = expf(lrelu(g_asrc2[sa0] + adst2n));
    }
    if (l + 32 < d) {
        sa1 = g_csr_src[p0 + l + 32];
        ea1 = expf(lrelu(g_asrc2[sa1] + adst2n));
    }

    float a0 = 0.f, a1 = 0.f, den = 0.f;
    int dmain = d < 64 ? d : 64;
#pragma unroll 4
    for (int j = 0; j < dmain; j++) {
        int   src = __shfl_sync(FULLMASK, (j < 32) ? sa0 : sa1, j & 31);
        float ex  = __shfl_sync(FULLMASK, (j < 32) ? ea0 : ea1, j & 31);
        den += ex;
        unsigned hv = g_h2h[src * 32 + l];
        float2 v = __half22float2(*(__half2*)&hv);
        a0 += ex * v.x;
        a1 += ex * v.y;
    }
    for (int j = 64; j < d; j++) {
        int src = g_csr_src[p0 + j];
        float ex = expf(lrelu(g_asrc2[src] + adst2n));
        den += ex;
        unsigned hv = g_h2h[src * 32 + l];
        float2 v = __half22float2(*(__half2*)&hv);
        a0 += ex * v.x;
        a1 += ex * v.y;
    }
    float inv = 1.f / (den + 1e-16f);
    float2 o;
    o.x = elu(a0 * inv + b2[2 * l + 0]);
    o.y = elu(a1 * inv + b2[2 * l + 1]);
    ((float2*)(out + n * 64))[l] = o;
}

// ---------------- launch ----------------
extern "C" void kernel_launch(void* const* d_in, const int* in_sizes, int n_in,
                              void* d_out, int out_size) {
    const float* x   = (const float*)d_in[0];
    const void*  ei  = d_in[1];
    const float* W1  = (const float*)d_in[2];
    const float* as1 = (const float*)d_in[3];
    const float* ad1 = (const float*)d_in[4];
    const float* b1  = (const float*)d_in[5];
    const float* W2  = (const float*)d_in[6];
    const float* as2 = (const float*)d_in[7];
    const float* ad2 = (const float*)d_in[8];
    const float* b2  = (const float*)d_in[9];
    float* out = (float*)d_out;

    k_gemm1_hist<<<G1B + (ETOT + 255) / 256, 256>>>(x, W1, as1, ad1, ei);
    k_scan<<<NB, 256>>>();
    k_scatter<<<(ETOT + 511) / 512, 256>>>(ei);
    k_agg1<<<NN / 8, 256>>>(b1);
    k_gemm2<<<G1B, 256>>>(W2, as2, ad2);
    k_agg2<<<NN / 8, 256>>>(b2, out);
}

// round 13
// speedup vs baseline: 1.0139x; 1.0139x over previous
#include <cuda_runtime.h>
#include <cuda_fp16.h>

#define NN 50000
#define EE 400000
#define ETOT 450000            // EE + NN self loops
#define NB 196                 // ceil(NN/256)
#define G1B 782                // ceil(NN/64)
#define FULLMASK 0xffffffffu

// ---------------- static scratch (no allocations allowed) ----------------
__device__ uint4    g_h1h[NN * 32];      // layer1 features fp16 [N,4,64]
__device__ float4   g_asrc1[NN];         // [N,4]
__device__ float4   g_adst1[NN];         // [N,4]
__device__ float    g_h1out[NN * 64];    // layer1 output after mean+bias+ELU
__device__ unsigned g_h2h[NN * 32];      // layer2 features fp16 [N,64], 32 half2/node
__device__ float    g_asrc2[NN];
__device__ float    g_adst2[NN];
__device__ int      g_counts[NN];        // starts zero; re-zeroed by k_scan_a each launch
__device__ int      g_offsets[NN + 1];
__device__ int      g_cursor[NN];
__device__ int      g_csr_src[ETOT];
__device__ int      g_bsum[256];

union F2U { float2 f; unsigned long long u; };

__device__ __forceinline__ float lrelu(float v) { return v > 0.f ? v : 0.2f * v; }
__device__ __forceinline__ float elu(float v)   { return v > 0.f ? v : expm1f(v); }

__device__ __forceinline__ int edge_val(const void* ei, int idx, bool is64) {
    if (is64) return (int)((const long long*)ei)[idx];
    return ((const int*)ei)[idx];
}

__device__ __forceinline__ float pick4(float4 v, int s) {
    return (s == 0) ? v.x : (s == 1) ? v.y : (s == 2) ? v.z : v.w;
}

// Per-block dtype probe: int64 non-negative values < 2^31 have zero odd words.
__device__ __forceinline__ bool probe_is64(const unsigned* ei32, int t, int* s_flag) {
    if (t == 0) *s_flag = 0;
    __syncthreads();
    if (t < 64) {
        unsigned a = __ldg(&ei32[2 * t + 1]);
        if (a) atomicOr(s_flag, 1);
    }
    __syncthreads();
    return *s_flag == 0;
}

// ---------------- fused: layer1 GEMM (+att coeffs, per-block u) + dst histogram ----------------
__global__ void k_gemm1_hist(const float* __restrict__ x, const float* __restrict__ W1,
                             const float* __restrict__ as1, const float* __restrict__ ad1,
                             const void* __restrict__ ei) {
    int t = threadIdx.x;
    int b = blockIdx.x;
    if (b < G1B) {
        __shared__ float Ws[4096];
        __shared__ float xs[1024];
        __shared__ float s_u[128];           // usrc1[64] (k*4+h), udst1[64]
        int base = b * 64;
        for (int i = t; i < 4096; i += 256) Ws[i] = W1[i];
        for (int i = t; i < 1024; i += 256) {
            int gi = base * 16 + i;
            xs[i] = (gi < NN * 16) ? x[gi] : 0.f;
        }
        __syncthreads();
        if (t < 64) {
            int k = t >> 2, h = t & 3;
            float s = 0.f, d = 0.f;
#pragma unroll 16
            for (int c = 0; c < 64; c++) {
                float w = Ws[k * 256 + h * 64 + c];
                s += w * __ldg(&as1[h * 64 + c]);
                d += w * __ldg(&ad1[h * 64 + c]);
            }
            s_u[t]      = s;
            s_u[64 + t] = d;
        }
        int ct = t & 31, nt = t >> 5;
        float acc[8][8];
#pragma unroll
        for (int i = 0; i < 8; i++)
#pragma unroll
            for (int j = 0; j < 8; j++) acc[i][j] = 0.f;
#pragma unroll
        for (int k = 0; k < 16; k++) {
            float4 wa = *(const float4*)&Ws[k * 256 + ct * 8];
            float4 wb = *(const float4*)&Ws[k * 256 + ct * 8 + 4];
#pragma unroll
            for (int i = 0; i < 8; i++) {
                float xv = xs[(nt * 8 + i) * 16 + k];
                acc[i][0] += xv * wa.x; acc[i][1] += xv * wa.y;
                acc[i][2] += xv * wa.z; acc[i][3] += xv * wa.w;
                acc[i][4] += xv * wb.x; acc[i][5] += xv * wb.y;
                acc[i][6] += xv * wb.z; acc[i][7] += xv * wb.w;
            }
        }
#pragma unroll
        for (int i = 0; i < 8; i++) {
            int node = base + nt * 8 + i;
            if (node < NN) {
                __half2 h0 = __floats2half2_rn(acc[i][0], acc[i][1]);
                __half2 h1 = __floats2half2_rn(acc[i][2], acc[i][3]);
                __half2 h2 = __floats2half2_rn(acc[i][4], acc[i][5]);
                __half2 h3 = __floats2half2_rn(acc[i][6], acc[i][7]);
                uint4 u;
                u.x = *(unsigned*)&h0; u.y = *(unsigned*)&h1;
                u.z = *(unsigned*)&h2; u.w = *(unsigned*)&h3;
                g_h1h[node * 32 + ct] = u;
            }
        }
        __syncthreads();
        {
            int nl = t >> 2, h = t & 3;
            int node = base + nl;
            if (node < NN) {
                float s = 0.f, d = 0.f;
#pragma unroll
                for (int k = 0; k < 16; k++) {
                    float xv = xs[nl * 16 + k];
                    s += xv * s_u[k * 4 + h];
                    d += xv * s_u[64 + k * 4 + h];
                }
                ((float*)g_asrc1)[node * 4 + h] = s;
                ((float*)g_adst1)[node * 4 + h] = d;
            }
        }
    } else {
        __shared__ int s_flag;
        bool is64 = probe_is64((const unsigned*)ei, t, &s_flag);
        int e = (b - G1B) * 256 + t;
        if (e < ETOT) {
            int dst = (e < EE) ? edge_val(ei, EE + e, is64) : (e - EE);
            atomicAdd(&g_counts[dst], 1);
        }
    }
}

// ---------------- scan A: warp-shuffle block scan + block sums (+re-zero counts) ----------------
__global__ void k_scan_a() {
    __shared__ int wsum[8];
    int t = threadIdx.x;
    int b = blockIdx.x;
    int i = b * 256 + t;
    int c = (i < NN) ? g_counts[i] : 0;
    if (i < NN) g_counts[i] = 0;             // ready for next graph replay
    int v = c;
#pragma unroll
    for (int o = 1; o < 32; o <<= 1) {
        int y = __shfl_up_sync(FULLMASK, v, o);
        if ((t & 31) >= o) v += y;
    }
    if ((t & 31) == 31) wsum[t >> 5] = v;
    __syncthreads();
    if (t < 8) {
        int w = wsum[t];
#pragma unroll
        for (int o = 1; o < 8; o <<= 1) {
            int y = __shfl_up_sync(0x000000ffu, w, o);
            if (t >= o) w += y;
        }
        wsum[t] = w;
    }
    __syncthreads();
    int incl = v + ((t >= 32) ? wsum[(t >> 5) - 1] : 0);
    if (i < NN) g_offsets[i] = incl - c;
    if (t == 255) g_bsum[b] = incl;
}

// ---------------- scan C: inline top-level prefix (shuffle) + add-back ----------------
__global__ void k_scan_c() {
    __shared__ int wsum[8];
    __shared__ int bval;
    int t = threadIdx.x;
    int b = blockIdx.x;
    int c = (t < NB) ? g_bsum[t] : 0;
    int v = c;
#pragma unroll
    for (int o = 1; o < 32; o <<= 1) {
        int y = __shfl_up_sync(FULLMASK, v, o);
        if ((t & 31) >= o) v += y;
    }
    if ((t & 31) == 31) wsum[t >> 5] = v;
    __syncthreads();
    if (t < 8) {
        int w = wsum[t];
#pragma unroll
        for (int o = 1; o < 8; o <<= 1) {
            int y = __shfl_up_sync(0x000000ffu, w, o);
            if (t >= o) w += y;
        }
        wsum[t] = w;
    }
    __syncthreads();
    int incl = v + ((t >= 32) ? wsum[(t >> 5) - 1] : 0);
    if (t == b) bval = incl - c;
    __syncthreads();
    int boff = bval;
    int i = b * 256 + t;
    if (i < NN) {
        int off = g_offsets[i] + boff;
        g_offsets[i] = off;
        g_cursor[i]  = off;
    }
    if (b == 0 && t == 0) g_offsets[NN] = ETOT;
}

// ---------------- scatter edges to CSR (src only), 2 edges/thread ----------------
__global__ void k_scatter(const void* __restrict__ ei) {
    __shared__ int s_flag;
    int t = threadIdx.x;
    bool is64 = probe_is64((const unsigned*)ei, t, &s_flag);
    int e0 = blockIdx.x * 512 + t;
#pragma unroll
    for (int k = 0; k < 2; k++) {
        int e = e0 + k * 256;
        if (e < ETOT) {
            int src, dst;
            if (e < EE) { src = edge_val(ei, e, is64); dst = edge_val(ei, EE + e, is64); }
            else        { src = e - EE; dst = e - EE; }
            int pos = atomicAdd(&g_cursor[dst], 1);
            g_csr_src[pos] = src;
        }
    }
}

// ---------------- layer1 aggregation: warp per node, batch-of-8 exp, packed f32x2 FMA --------
__global__ void __launch_bounds__(256, 6) k_agg1(const float* __restrict__ b1) {
    int warp = (blockIdx.x * blockDim.x + threadIdx.x) >> 5;
    int l = threadIdx.x & 31;
    if (warp >= NN) return;
    int n = warp;
    int p0 = g_offsets[n], p1 = g_offsets[n + 1];
    int d = p1 - p0;
    int hsel = l >> 3;
    int el = l & 7;
    float adh = pick4(g_adst1[n], hsel);

    unsigned long long accu[4] = {0ULL, 0ULL, 0ULL, 0ULL};   // 8 fp32 accumulators, packed
    float denp = 0.f;

    int base = 0;
    for (; base + 8 <= d; base += 8) {
        int s = g_csr_src[p0 + base + el];
        float ash = pick4(__ldg(&g_asrc1[s]), hsel);
        float ex = expf(lrelu(ash + adh));
        denp += ex;
#pragma unroll
        for (int j = 0; j < 8; j++) {
            int   src = __shfl_sync(FULLMASK, s,  hsel * 8 + j);
            float exh = __shfl_sync(FULLMASK, ex, hsel * 8 + j);
            F2U e2; e2.f = make_float2(exh, exh);
            uint4 u = g_h1h[src * 32 + l];
            __half2* hh = (__half2*)&u;
#pragma unroll
            for (int k = 0; k < 4; k++) {
                F2U v; v.f = __half22float2(hh[k]);
                asm("fma.rn.f32x2 %0, %1, %2, %0;" : "+l"(accu[k]) : "l"(v.u), "l"(e2.u));
            }
        }
    }
    if (base < d) {
        int jm = d - base;
        int s = 0; float ex = 0.f;
        if (el < jm) {
            s = g_csr_src[p0 + base + el];
            float ash = pick4(__ldg(&g_asrc1[s]), hsel);
            ex = expf(lrelu(ash + adh));
        }
        denp += ex;
        for (int j = 0; j < jm; j++) {
            int   src = __shfl_sync(FULLMASK, s,  hsel * 8 + j);
            float exh = __shfl_sync(FULLMASK, ex, hsel * 8 + j);
            F2U e2; e2.f = make_float2(exh, exh);
            uint4 u = g_h1h[src * 32 + l];
            __half2* hh = (__half2*)&u;
#pragma unroll
            for (int k = 0; k < 4; k++) {
                F2U v; v.f = __half22float2(hh[k]);
                asm("fma.rn.f32x2 %0, %1, %2, %0;" : "+l"(accu[k]) : "l"(v.u), "l"(e2.u));
            }
        }
    }

    float den = denp;
    den += __shfl_xor_sync(FULLMASK, den, 1);
    den += __shfl_xor_sync(FULLMASK, den, 2);
    den += __shfl_xor_sync(FULLMASK, den, 4);

    float acc[8];
#pragma unroll
    for (int k = 0; k < 4; k++) {
        F2U a; a.u = accu[k];
        acc[2 * k]     = a.f.x;
        acc[2 * k + 1] = a.f.y;
    }

    float inv = 0.25f / (den + 1e-16f);
    float r[8];
#pragma unroll
    for (int j = 0; j < 8; j++) {
        r[j] = acc[j] * inv;
        r[j] += __shfl_xor_sync(FULLMASK, r[j], 8);
        r[j] += __shfl_xor_sync(FULLMASK, r[j], 16);
    }
    if (l < 8) {
        float4 o0, o1;
        o0.x = elu(r[0] + b1[l * 8 + 0]);
        o0.y = elu(r[1] + b1[l * 8 + 1]);
        o0.z = elu(r[2] + b1[l * 8 + 2]);
        o0.w = elu(r[3] + b1[l * 8 + 3]);
        o1.x = elu(r[4] + b1[l * 8 + 4]);
        o1.y = elu(r[5] + b1[l * 8 + 5]);
        o1.z = elu(r[6] + b1[l * 8 + 6]);
        o1.w = elu(r[7] + b1[l * 8 + 7]);
        float4* op = (float4*)(g_h1out + n * 64) + l * 2;
        op[0] = o0;
        op[1] = o1;
    }
}

// ---------------- layer2 GEMM (per-block u, fp16 out) + att coeffs ----------------
__global__ void k_gemm2(const float* __restrict__ W2,
                        const float* __restrict__ as2, const float* __restrict__ ad2) {
    __shared__ float Ws[4096];
    __shared__ float xs[4096];
    __shared__ float s_u[128];
    int t = threadIdx.x;
    int base = blockIdx.x * 64;
    for (int i = t; i < 4096; i += 256) {
        Ws[i] = W2[i];
        int gi = base * 64 + i;
        xs[i] = (gi < NN * 64) ? g_h1out[gi] : 0.f;
    }
    __syncthreads();
    if (t < 128) {
        int k = t & 63;
        const float* av = (t < 64) ? as2 : ad2;
        float s = 0.f;
#pragma unroll 16
        for (int c = 0; c < 64; c++) s += Ws[k * 64 + c] * __ldg(&av[c]);
        s_u[t] = s;
    }
    int ct = t & 15, nt = t >> 4;
    float acc[4][4];
#pragma unroll
    for (int i = 0; i < 4; i++)
#pragma unroll
        for (int j = 0; j < 4; j++) acc[i][j] = 0.f;
#pragma unroll 8
    for (int k = 0; k < 64; k++) {
        float4 w = *(const float4*)&Ws[k * 64 + ct * 4];
#pragma unroll
        for (int i = 0; i < 4; i++) {
            float xv = xs[(nt * 4 + i) * 64 + k];
            acc[i][0] += xv * w.x; acc[i][1] += xv * w.y;
            acc[i][2] += xv * w.z; acc[i][3] += xv * w.w;
        }
    }
#pragma unroll
    for (int i = 0; i < 4; i++) {
        int node = base + nt * 4 + i;
        if (node < NN) {
            __half2 h0 = __floats2half2_rn(acc[i][0], acc[i][1]);
            __half2 h1 = __floats2half2_rn(acc[i][2], acc[i][3]);
            uint2 o;
            o.x = *(unsigned*)&h0;
            o.y = *(unsigned*)&h1;
            *(uint2*)&g_h2h[node * 32 + ct * 2] = o;
        }
    }
    __syncthreads();
    if (t < 128) {
        int nl = t >> 1;
        bool isdst = t & 1;
        int node = base + nl;
        if (node < NN) {
            const float* u = s_u + (isdst ? 64 : 0);
            float a = 0.f;
#pragma unroll 16
            for (int k = 0; k < 64; k++) a += xs[nl * 64 + k] * u[k];
            if (isdst) g_adst2[node] = a; else g_asrc2[node] = a;
        }
    }
}

// ---------------- layer2 aggregation with inline exp, fp16 gathers ----------------
__global__ void k_agg2(const float* __restrict__ b2, float* __restrict__ out) {
    int warp = (blockIdx.x * blockDim.x + threadIdx.x) >> 5;
    int l = threadIdx.x & 31;
    if (warp >= NN) return;
    int n = warp;
    int p0 = g_offsets[n], p1 = g_offsets[n + 1];
    int d = p1 - p0;
    float adst2n = g_adst2[n];

    int   sa0 = 0,  sa1 = 0;
    float ea0 = 0.f, ea1 = 0.f;
    if (l < d) {
        sa0 = g_csr_src[p0 + l];
        ea0 = expf(lrelu(g_asrc2[sa0] + adst2n));
    }
    if (l + 32 < d) {
        sa1 = g_csr_src[p0 + l + 32];
        ea1 = expf(lrelu(g_asrc2[sa1] + adst2n));
    }

    float a0 = 0.f, a1 = 0.f, den = 0.f;
    int dmain = d < 64 ? d : 64;
#pragma unroll 4
    for (int j = 0; j < dmain; j++) {
        int   src = __shfl_sync(FULLMASK, (j < 32) ? sa0 : sa1, j & 31);
        float ex  = __shfl_sync(FULLMASK, (j < 32) ? ea0 : ea1, j & 31);
        den += ex;
        unsigned hv = g_h2h[src * 32 + l];
        float2 v = __half22float2(*(__half2*)&hv);
        a0 += ex * v.x;
        a1 += ex * v.y;
    }
    for (int j = 64; j < d; j++) {
        int src = g_csr_src[p0 + j];
        float ex = expf(lrelu(g_asrc2[src] + adst2n));
        den += ex;
        unsigned hv = g_h2h[src * 32 + l];
        float2 v = __half22float2(*(__half2*)&hv);
        a0 += ex * v.x;
        a1 += ex * v.y;
    }
    float inv = 1.f / (den + 1e-16f);
    float2 o;
    o.x = elu(a0 * inv + b2[2 * l + 0]);
    o.y = elu(a1 * inv + b2[2 * l + 1]);
    ((float2*)(out + n * 64))[l] = o;
}

// ---------------- launch ----------------
extern "C" void kernel_launch(void* const* d_in, const int* in_sizes, int n_in,
                              void* d_out, int out_size) {
    const float* x   = (const float*)d_in[0];
    const void*  ei  = d_in[1];
    const float* W1  = (const float*)d_in[2];
    const float* as1 = (const float*)d_in[3];
    const float* ad1 = (const float*)d_in[4];
    const float* b1  = (const float*)d_in[5];
    const float* W2  = (const float*)d_in[6];
    const float* as2 = (const float*)d_in[7];
    const float* ad2 = (const float*)d_in[8];
    const float* b2  = (const float*)d_in[9];
    float* out = (float*)d_out;

    k_gemm1_hist<<<G1B + (ETOT + 255) / 256, 256>>>(x, W1, as1, ad1, ei);
    k_scan_a<<<NB, 256>>>();
    k_scan_c<<<NB, 256>>>();
    k_scatter<<<(ETOT + 511) / 512, 256>>>(ei);
    k_agg1<<<NN / 8, 256>>>(b1);
    k_gemm2<<<G1B, 256>>>(W2, as2, ad2);
    k_agg2<<<NN / 8, 256>>>(b2, out);
}

// round 16
// speedup vs baseline: 1.0454x; 1.0311x over previous
#include <cuda_runtime.h>
#include <cuda_fp16.h>

#define NN 50000
#define EE 400000
#define ETOT 450000            // EE + NN self loops
#define NB 196                 // ceil(NN/256)
#define G1B 782                // ceil(NN/64)
#define FULLMASK 0xffffffffu

// ---------------- static scratch (no allocations allowed) ----------------
__device__ uint4    g_h1h[NN * 32];      // layer1 features fp16 [N,4,64]
__device__ float4   g_asrc1[NN];         // [N,4]
__device__ float4   g_adst1[NN];         // [N,4]
__device__ float    g_h1out[NN * 64];    // layer1 output after mean+bias+ELU
__device__ unsigned g_h2h[NN * 32];      // layer2 features fp16 [N,64] as 32 half2 words/node
__device__ float    g_asrc2[NN];
__device__ float    g_adst2[NN];
__device__ int      g_counts[NN];
__device__ int      g_offsets[NN + 1];
__device__ int      g_cursor[NN];
__device__ int      g_csr_src[ETOT];
__device__ int      g_bsum[256];
__device__ float    g_u[256];            // usrc1[64](k*4+h), udst1[64], usrc2[64], udst2[64]
__device__ int      g_is64;              // edge_index dtype flag

union F2U { float2 f; unsigned long long u; };

__device__ __forceinline__ float lrelu(float v) { return v > 0.f ? v : 0.2f * v; }
__device__ __forceinline__ float elu(float v)   { return v > 0.f ? v : expm1f(v); }

__device__ __forceinline__ int edge_val(const void* ei, int idx) {
    if (g_is64) return (int)((const long long*)ei)[idx];
    return ((const int*)ei)[idx];
}

__device__ __forceinline__ float pick4(float4 v, int s) {
    return (s == 0) ? v.x : (s == 1) ? v.y : (s == 2) ? v.z : v.w;
}

// ---------------- init: detect dtype + folded attention vectors + zero counts ----------------
__global__ void k_init(const unsigned int* __restrict__ ei32,
                       const float* __restrict__ W1, const float* __restrict__ as1,
                       const float* __restrict__ ad1, const float* __restrict__ W2,
                       const float* __restrict__ as2, const float* __restrict__ ad2) {
    int t = threadIdx.x;
    int b = blockIdx.x;
    if (b == 0) {
        if (t < 64) {
            int k = t >> 2, h = t & 3;
            float s = 0.f, d = 0.f;
            for (int c = 0; c < 64; c++) {
                float w = W1[k * 256 + h * 64 + c];
                s += w * as1[h * 64 + c];
                d += w * ad1[h * 64 + c];
            }
            g_u[k * 4 + h]      = s;
            g_u[64 + k * 4 + h] = d;
            float s2 = 0.f, d2 = 0.f;
            for (int c = 0; c < 64; c++) {
                float w = W2[t * 64 + c];
                s2 += w * as2[c];
                d2 += w * ad2[c];
            }
            g_u[128 + t] = s2;
            g_u[192 + t] = d2;
        } else if (t < 96) {
            int l = t - 64;
            unsigned a = ei32[2 * l + 1] | ei32[2 * (l + 32) + 1];
            unsigned nz = __ballot_sync(FULLMASK, a != 0u);
            if (l == 0) g_is64 = (nz == 0u);
        }
    } else {
        int i = (b - 1) * 256 + t;
        if (i < NN) g_counts[i] = 0;
    }
}

// ---------------- fused: layer1 GEMM (64 nodes/block, 8x8 reg tile) + dst histogram ----------------
__global__ void k_gemm1_hist(const float* __restrict__ x, const float* __restrict__ W1,
                             const void* __restrict__ ei) {
    int t = threadIdx.x;
    int b = blockIdx.x;
    if (b < G1B) {
        __shared__ float Ws[4096];
        __shared__ float xs[1024];
        int base = b * 64;
        for (int i = t; i < 4096; i += 256) Ws[i] = W1[i];
        for (int i = t; i < 1024; i += 256) {
            int gi = base * 16 + i;
            xs[i] = (gi < NN * 16) ? x[gi] : 0.f;
        }
        __syncthreads();
        int ct = t & 31, nt = t >> 5;
        float acc[8][8];
#pragma unroll
        for (int i = 0; i < 8; i++)
#pragma unroll
            for (int j = 0; j < 8; j++) acc[i][j] = 0.f;
#pragma unroll
        for (int k = 0; k < 16; k++) {
            float4 wa = *(const float4*)&Ws[k * 256 + ct * 8];
            float4 wb = *(const float4*)&Ws[k * 256 + ct * 8 + 4];
#pragma unroll
            for (int i = 0; i < 8; i++) {
                float xv = xs[(nt * 8 + i) * 16 + k];
                acc[i][0] += xv * wa.x; acc[i][1] += xv * wa.y;
                acc[i][2] += xv * wa.z; acc[i][3] += xv * wa.w;
                acc[i][4] += xv * wb.x; acc[i][5] += xv * wb.y;
                acc[i][6] += xv * wb.z; acc[i][7] += xv * wb.w;
            }
        }
#pragma unroll
        for (int i = 0; i < 8; i++) {
            int node = base + nt * 8 + i;
            if (node < NN) {
                __half2 h0 = __floats2half2_rn(acc[i][0], acc[i][1]);
                __half2 h1 = __floats2half2_rn(acc[i][2], acc[i][3]);
                __half2 h2 = __floats2half2_rn(acc[i][4], acc[i][5]);
                __half2 h3 = __floats2half2_rn(acc[i][6], acc[i][7]);
                uint4 u;
                u.x = *(unsigned*)&h0; u.y = *(unsigned*)&h1;
                u.z = *(unsigned*)&h2; u.w = *(unsigned*)&h3;
                g_h1h[node * 32 + ct] = u;
            }
        }
        {
            int nl = t >> 2, h = t & 3;
            int node = base + nl;
            if (node < NN) {
                float s = 0.f, d = 0.f;
#pragma unroll
                for (int k = 0; k < 16; k++) {
                    float xv = xs[nl * 16 + k];
                    s += xv * g_u[k * 4 + h];
                    d += xv * g_u[64 + k * 4 + h];
                }
                ((float*)g_asrc1)[node * 4 + h] = s;
                ((float*)g_adst1)[node * 4 + h] = d;
            }
        }
    } else {
        int e = (b - G1B) * 256 + t;
        if (e < ETOT) {
            int dst = (e < EE) ? edge_val(ei, EE + e) : (e - EE);
            atomicAdd(&g_counts[dst], 1);
        }
    }
}

// ---------------- scan A: warp-shuffle block scan + block sums ----------------
__global__ void k_scan_a() {
    __shared__ int wsum[8];
    int t = threadIdx.x;
    int b = blockIdx.x;
    int i = b * 256 + t;
    int c = (i < NN) ? g_counts[i] : 0;
    int v = c;
#pragma unroll
    for (int o = 1; o < 32; o <<= 1) {
        int y = __shfl_up_sync(FULLMASK, v, o);
        if ((t & 31) >= o) v += y;
    }
    if ((t & 31) == 31) wsum[t >> 5] = v;
    __syncthreads();
    if (t < 8) {
        int w = wsum[t];
#pragma unroll
        for (int o = 1; o < 8; o <<= 1) {
            int y = __shfl_up_sync(0x000000ffu, w, o);
            if (t >= o) w += y;
        }
        wsum[t] = w;
    }
    __syncthreads();
    int incl = v + ((t >= 32) ? wsum[(t >> 5) - 1] : 0);
    if (i < NN) g_offsets[i] = incl - c;
    if (t == 255) g_bsum[b] = incl;
}

// ---------------- scan C: inline top-level prefix (shuffle) + add-back ----------------
__global__ void k_scan_c() {
    __shared__ int wsum[8];
    __shared__ int bval;
    int t = threadIdx.x;
    int b = blockIdx.x;
    int c = (t < NB) ? g_bsum[t] : 0;
    int v = c;
#pragma unroll
    for (int o = 1; o < 32; o <<= 1) {
        int y = __shfl_up_sync(FULLMASK, v, o);
        if ((t & 31) >= o) v += y;
    }
    if ((t & 31) == 31) wsum[t >> 5] = v;
    __syncthreads();
    if (t < 8) {
        int w = wsum[t];
#pragma unroll
        for (int o = 1; o < 8; o <<= 1) {
            int y = __shfl_up_sync(0x000000ffu, w, o);
            if (t >= o) w += y;
        }
        wsum[t] = w;
    }
    __syncthreads();
    int incl = v + ((t >= 32) ? wsum[(t >> 5) - 1] : 0);
    if (t == b) bval = incl - c;          // exclusive prefix for this block
    __syncthreads();
    int boff = bval;
    int i = b * 256 + t;
    if (i < NN) {
        int off = g_offsets[i] + boff;
        g_offsets[i] = off;
        g_cursor[i]  = off;
    }
    if (b == 0 && t == 0) g_offsets[NN] = ETOT;
}

// ---------------- scatter edges to CSR (src only) ----------------
__global__ void k_scatter(const void* __restrict__ ei) {
    int e = blockIdx.x * blockDim.x + threadIdx.x;
    if (e >= ETOT) return;
    int src, dst;
    if (e < EE) { src = edge_val(ei, e); dst = edge_val(ei, EE + e); }
    else        { src = e - EE; dst = e - EE; }
    int pos = atomicAdd(&g_cursor[dst], 1);
    g_csr_src[pos] = src;
}

// ---------------- layer1 aggregation: warp per node, batch-of-8 exp, packed f32x2 FMA ------
__global__ void __launch_bounds__(256, 6) k_agg1(const float* __restrict__ b1) {
    int warp = (blockIdx.x * blockDim.x + threadIdx.x) >> 5;
    int l = threadIdx.x & 31;
    if (warp >= NN) return;
    int n = warp;
    int p0 = g_offsets[n], p1 = g_offsets[n + 1];
    int d = p1 - p0;
    int hsel = l >> 3;
    int el = l & 7;
    float adh = pick4(g_adst1[n], hsel);

    unsigned long long accu[4] = {0ULL, 0ULL, 0ULL, 0ULL};   // 8 fp32 accumulators, packed
    float denp = 0.f;

    int base = 0;
    for (; base + 8 <= d; base += 8) {
        int s = g_csr_src[p0 + base + el];
        float ash = pick4(__ldg(&g_asrc1[s]), hsel);
        float ex = expf(lrelu(ash + adh));
        denp += ex;
#pragma unroll
        for (int j = 0; j < 8; j++) {
            int   src = __shfl_sync(FULLMASK, s,  hsel * 8 + j);
            float exh = __shfl_sync(FULLMASK, ex, hsel * 8 + j);
            F2U e2; e2.f = make_float2(exh, exh);
            uint4 u = g_h1h[src * 32 + l];
            __half2* hh = (__half2*)&u;
#pragma unroll
            for (int k = 0; k < 4; k++) {
                F2U v; v.f = __half22float2(hh[k]);
                asm("fma.rn.f32x2 %0, %1, %2, %0;" : "+l"(accu[k]) : "l"(v.u), "l"(e2.u));
            }
        }
    }
    if (base < d) {
        int jm = d - base;
        int s = 0; float ex = 0.f;
        if (el < jm) {
            s = g_csr_src[p0 + base + el];
            float ash = pick4(__ldg(&g_asrc1[s]), hsel);
            ex = expf(lrelu(ash + adh));
        }
        denp += ex;
        for (int j = 0; j < jm; j++) {
            int   src = __shfl_sync(FULLMASK, s,  hsel * 8 + j);
            float exh = __shfl_sync(FULLMASK, ex, hsel * 8 + j);
            F2U e2; e2.f = make_float2(exh, exh);
            uint4 u = g_h1h[src * 32 + l];
            __half2* hh = (__half2*)&u;
#pragma unroll
            for (int k = 0; k < 4; k++) {
                F2U v; v.f = __half22float2(hh[k]);
                asm("fma.rn.f32x2 %0, %1, %2, %0;" : "+l"(accu[k]) : "l"(v.u), "l"(e2.u));
            }
        }
    }

    float den = denp;
    den += __shfl_xor_sync(FULLMASK, den, 1);
    den += __shfl_xor_sync(FULLMASK, den, 2);
    den += __shfl_xor_sync(FULLMASK, den, 4);

    float acc[8];
#pragma unroll
    for (int k = 0; k < 4; k++) {
        F2U a; a.u = accu[k];
        acc[2 * k]     = a.f.x;
        acc[2 * k + 1] = a.f.y;
    }

    float inv = 0.25f / (den + 1e-16f);
    float r[8];
#pragma unroll
    for (int j = 0; j < 8; j++) {
        r[j] = acc[j] * inv;
        r[j] += __shfl_xor_sync(FULLMASK, r[j], 8);
        r[j] += __shfl_xor_sync(FULLMASK, r[j], 16);
    }
    if (l < 8) {
        float4 o0, o1;
        o0.x = elu(r[0] + b1[l * 8 + 0]);
        o0.y = elu(r[1] + b1[l * 8 + 1]);
        o0.z = elu(r[2] + b1[l * 8 + 2]);
        o0.w = elu(r[3] + b1[l * 8 + 3]);
        o1.x = elu(r[4] + b1[l * 8 + 4]);
        o1.y = elu(r[5] + b1[l * 8 + 5]);
        o1.z = elu(r[6] + b1[l * 8 + 6]);
        o1.w = elu(r[7] + b1[l * 8 + 7]);
        float4* op = (float4*)(g_h1out + n * 64) + l * 2;
        op[0] = o0;
        op[1] = o1;
    }
}

// ---------------- layer2 GEMM (64 nodes/block, 4x4 reg tile, fp16 out) + att coeffs ----------------
__global__ void k_gemm2(const float* __restrict__ W2) {
    __shared__ float Ws[4096];
    __shared__ float xs[4096];
    int t = threadIdx.x;
    int base = blockIdx.x * 64;
    for (int i = t; i < 4096; i += 256) {
        Ws[i] = W2[i];
        int gi = base * 64 + i;
        xs[i] = (gi < NN * 64) ? g_h1out[gi] : 0.f;
    }
    __syncthreads();
    int ct = t & 15, nt = t >> 4;
    float acc[4][4];
#pragma unroll
    for (int i = 0; i < 4; i++)
#pragma unroll
        for (int j = 0; j < 4; j++) acc[i][j] = 0.f;
#pragma unroll 8
    for (int k = 0; k < 64; k++) {
        float4 w = *(const float4*)&Ws[k * 64 + ct * 4];
#pragma unroll
        for (int i = 0; i < 4; i++) {
            float xv = xs[(nt * 4 + i) * 64 + k];
            acc[i][0] += xv * w.x; acc[i][1] += xv * w.y;
            acc[i][2] += xv * w.z; acc[i][3] += xv * w.w;
        }
    }
#pragma unroll
    for (int i = 0; i < 4; i++) {
        int node = base + nt * 4 + i;
        if (node < NN) {
            __half2 h0 = __floats2half2_rn(acc[i][0], acc[i][1]);
            __half2 h1 = __floats2half2_rn(acc[i][2], acc[i][3]);
            uint2 o;
            o.x = *(unsigned*)&h0;
            o.y = *(unsigned*)&h1;
            *(uint2*)&g_h2h[node * 32 + ct * 2] = o;
        }
    }
    if (t < 128) {
        int nl = t >> 1;
        bool isdst = t & 1;
        int node = base + nl;
        if (node < NN) {
            const float* u = g_u + 128 + (isdst ? 64 : 0);
            float a = 0.f;
#pragma unroll 16
            for (int k = 0; k < 64; k++) a += xs[nl * 64 + k] * u[k];
            if (isdst) g_adst2[node] = a; else g_asrc2[node] = a;
        }
    }
}

// ---------------- layer2 aggregation with inline exp, fp16 gathers, packed FMA ----------------
__global__ void k_agg2(const float* __restrict__ b2, float* __restrict__ out) {
    int warp = (blockIdx.x * blockDim.x + threadIdx.x) >> 5;
    int l = threadIdx.x & 31;
    if (warp >= NN) return;
    int n = warp;
    int p0 = g_offsets[n], p1 = g_offsets[n + 1];
    int d = p1 - p0;
    float adst2n = g_adst2[n];

    int   sa0 = 0,  sa1 = 0;
    float ea0 = 0.f, ea1 = 0.f;
    if (l < d) {
        sa0 = g_csr_src[p0 + l];
        ea0 = expf(lrelu(g_asrc2[sa0] + adst2n));
    }
    if (l + 32 < d) {
        sa1 = g_csr_src[p0 + l + 32];
        ea1 = expf(lrelu(g_asrc2[sa1] + adst2n));
    }

    unsigned long long accu = 0ULL;
    float den = 0.f;
    int dmain = d < 64 ? d : 64;
#pragma unroll 4
    for (int j = 0; j < dmain; j++) {
        int   src = __shfl_sync(FULLMASK, (j < 32) ? sa0 : sa1, j & 31);
        float ex  = __shfl_sync(FULLMASK, (j < 32) ? ea0 : ea1, j & 31);
        den += ex;
        unsigned hv = g_h2h[src * 32 + l];
        F2U v; v.f = __half22float2(*(__half2*)&hv);
        F2U e2; e2.f = make_float2(ex, ex);
        asm("fma.rn.f32x2 %0, %1, %2, %0;" : "+l"(accu) : "l"(v.u), "l"(e2.u));
    }
    for (int j = 64; j < d; j++) {
        int src = g_csr_src[p0 + j];
        float ex = expf(lrelu(g_asrc2[src] + adst2n));
        den += ex;
        unsigned hv = g_h2h[src * 32 + l];
        F2U v; v.f = __half22float2(*(__half2*)&hv);
        F2U e2; e2.f = make_float2(ex, ex);
        asm("fma.rn.f32x2 %0, %1, %2, %0;" : "+l"(accu) : "l"(v.u), "l"(e2.u));
    }
    F2U a; a.u = accu;
    float inv = 1.f / (den + 1e-16f);
    float2 o;
    o.x = elu(a.f.x * inv + b2[2 * l + 0]);
    o.y = elu(a.f.y * inv + b2[2 * l + 1]);
    ((float2*)(out + n * 64))[l] = o;
}

// ---------------- launch ----------------
extern "C" void kernel_launch(void* const* d_in, const int* in_sizes, int n_in,
                              void* d_out, int out_size) {
    const float* x   = (const float*)d_in[0];
    const void*  ei  = d_in[1];
    const float* W1  = (const float*)d_in[2];
    const float* as1 = (const float*)d_in[3];
    const float* ad1 = (const float*)d_in[4];
    const float* b1  = (const float*)d_in[5];
    const float* W2  = (const float*)d_in[6];
    const float* as2 = (const float*)d_in[7];
    const float* ad2 = (const float*)d_in[8];
    const float* b2  = (const float*)d_in[9];
    float* out = (float*)d_out;

    k_init<<<1 + NB, 256>>>((const unsigned int*)ei, W1, as1, ad1, W2, as2, ad2);
    k_gemm1_hist<<<G1B + (ETOT + 255) / 256, 256>>>(x, W1, ei);
    k_scan_a<<<NB, 256>>>();
    k_scan_c<<<NB, 256>>>();
    k_scatter<<<(ETOT + 255) / 256, 256>>>(ei);
    k_agg1<<<NN / 8, 256>>>(b1);
    k_gemm2<<<G1B, 256>>>(W2);
    k_agg2<<<NN / 8, 256>>>(b2, out);
}

// round 17
// speedup vs baseline: 1.0787x; 1.0318x over previous
#include <cuda_runtime.h>
#include <cuda_fp16.h>

#define NN 50000
#define EE 400000
#define ETOT 450000            // EE + NN self loops
#define NB 196                 // ceil(NN/256)
#define G1B 782                // ceil(NN/64)
#define FULLMASK 0xffffffffu

// ---------------- static scratch (no allocations allowed) ----------------
__device__ uint4    g_h1h[NN * 32];      // layer1 features fp16 [N,4,64]
__device__ float4   g_asrc1[NN];         // [N,4]
__device__ float4   g_adst1[NN];         // [N,4]
__device__ float    g_h1out[NN * 64];    // layer1 output after mean+bias+ELU
__device__ unsigned g_h2h[NN * 32];      // layer2 features fp16 [N,64] as 32 half2 words/node
__device__ float    g_asrc2[NN];
__device__ float    g_adst2[NN];
__device__ int      g_counts[NN];        // degree; starts zero, re-zeroed by k_agg2 each launch
__device__ int      g_offsets[NN];       // CSR start per node (block-arrival order)
__device__ int      g_cursor[NN];
__device__ int      g_csr_src[ETOT];
__device__ int      g_total;             // CSR allocation counter (zeroed by k_init)
__device__ float    g_u[256];            // usrc1[64](k*4+h), udst1[64], usrc2[64], udst2[64]
__device__ int      g_is64;              // edge_index dtype flag

__device__ __forceinline__ float lrelu(float v) { return v > 0.f ? v : 0.2f * v; }
__device__ __forceinline__ float elu(float v)   { return v > 0.f ? v : expm1f(v); }

__device__ __forceinline__ int edge_val(const void* ei, int idx) {
    if (g_is64) return (int)((const long long*)ei)[idx];
    return ((const int*)ei)[idx];
}

__device__ __forceinline__ float pick4(float4 v, int s) {
    return (s == 0) ? v.x : (s == 1) ? v.y : (s == 2) ? v.z : v.w;
}

// ---------------- init: detect dtype + folded attention vectors + zero total ----------------
__global__ void k_init(const unsigned int* __restrict__ ei32,
                       const float* __restrict__ W1, const float* __restrict__ as1,
                       const float* __restrict__ ad1, const float* __restrict__ W2,
                       const float* __restrict__ as2, const float* __restrict__ ad2) {
    int t = threadIdx.x;
    if (t < 64) {
        int k = t >> 2, h = t & 3;
        float s = 0.f, d = 0.f;
        for (int c = 0; c < 64; c++) {
            float w = W1[k * 256 + h * 64 + c];
            s += w * as1[h * 64 + c];
            d += w * ad1[h * 64 + c];
        }
        g_u[k * 4 + h]      = s;
        g_u[64 + k * 4 + h] = d;
        float s2 = 0.f, d2 = 0.f;
        for (int c = 0; c < 64; c++) {
            float w = W2[t * 64 + c];
            s2 += w * as2[c];
            d2 += w * ad2[c];
        }
        g_u[128 + t] = s2;
        g_u[192 + t] = d2;
    } else if (t < 96) {
        int l = t - 64;
        unsigned a = ei32[2 * l + 1] | ei32[2 * (l + 32) + 1];
        unsigned nz = __ballot_sync(FULLMASK, a != 0u);
        if (l == 0) g_is64 = (nz == 0u);
    } else if (t == 96) {
        g_total = 0;
    }
}

// ---------------- fused: layer1 GEMM (64 nodes/block, 8x8 reg tile) + dst histogram ----------------
__global__ void k_gemm1_hist(const float* __restrict__ x, const float* __restrict__ W1,
                             const void* __restrict__ ei) {
    int t = threadIdx.x;
    int b = blockIdx.x;
    if (b < G1B) {
        __shared__ float Ws[4096];
        __shared__ float xs[1024];
        int base = b * 64;
        for (int i = t; i < 4096; i += 256) Ws[i] = W1[i];
        for (int i = t; i < 1024; i += 256) {
            int gi = base * 16 + i;
            xs[i] = (gi < NN * 16) ? x[gi] : 0.f;
        }
        __syncthreads();
        int ct = t & 31, nt = t >> 5;
        float acc[8][8];
#pragma unroll
        for (int i = 0; i < 8; i++)
#pragma unroll
            for (int j = 0; j < 8; j++) acc[i][j] = 0.f;
#pragma unroll
        for (int k = 0; k < 16; k++) {
            float4 wa = *(const float4*)&Ws[k * 256 + ct * 8];
            float4 wb = *(const float4*)&Ws[k * 256 + ct * 8 + 4];
#pragma unroll
            for (int i = 0; i < 8; i++) {
                float xv = xs[(nt * 8 + i) * 16 + k];
                acc[i][0] += xv * wa.x; acc[i][1] += xv * wa.y;
                acc[i][2] += xv * wa.z; acc[i][3] += xv * wa.w;
                acc[i][4] += xv * wb.x; acc[i][5] += xv * wb.y;
                acc[i][6] += xv * wb.z; acc[i][7] += xv * wb.w;
            }
        }
#pragma unroll
        for (int i = 0; i < 8; i++) {
            int node = base + nt * 8 + i;
            if (node < NN) {
                __half2 h0 = __floats2half2_rn(acc[i][0], acc[i][1]);
                __half2 h1 = __floats2half2_rn(acc[i][2], acc[i][3]);
                __half2 h2 = __floats2half2_rn(acc[i][4], acc[i][5]);
                __half2 h3 = __floats2half2_rn(acc[i][6], acc[i][7]);
                uint4 u;
                u.x = *(unsigned*)&h0; u.y = *(unsigned*)&h1;
                u.z = *(unsigned*)&h2; u.w = *(unsigned*)&h3;
                g_h1h[node * 32 + ct] = u;
            }
        }
        {
            int nl = t >> 2, h = t & 3;
            int node = base + nl;
            if (node < NN) {
                float s = 0.f, d = 0.f;
#pragma unroll
                for (int k = 0; k < 16; k++) {
                    float xv = xs[nl * 16 + k];
                    s += xv * g_u[k * 4 + h];
                    d += xv * g_u[64 + k * 4 + h];
                }
                ((float*)g_asrc1)[node * 4 + h] = s;
                ((float*)g_adst1)[node * 4 + h] = d;
            }
        }
    } else {
        int e = (b - G1B) * 256 + t;
        if (e < ETOT) {
            int dst = (e < EE) ? edge_val(ei, EE + e) : (e - EE);
            atomicAdd(&g_counts[dst], 1);
        }
    }
}

// ---------------- single-launch scan: block-local scan + atomic block base ----------------
// CSR ranges are allocated in block ARRIVAL order via one atomicAdd per block. Ranges
// are disjoint; node order across blocks is irrelevant since aggregators use
// [offsets[n], offsets[n] + counts[n]).
__global__ void k_scan() {
    __shared__ int wsum[8];
    __shared__ int s_start;
    int t = threadIdx.x;
    int b = blockIdx.x;
    int i = b * 256 + t;
    int c = (i < NN) ? g_counts[i] : 0;
    int v = c;
#pragma unroll
    for (int o = 1; o < 32; o <<= 1) {
        int y = __shfl_up_sync(FULLMASK, v, o);
        if ((t & 31) >= o) v += y;
    }
    if ((t & 31) == 31) wsum[t >> 5] = v;
    __syncthreads();
    if (t < 8) {
        int w = wsum[t];
#pragma unroll
        for (int o = 1; o < 8; o <<= 1) {
            int y = __shfl_up_sync(0x000000ffu, w, o);
            if (t >= o) w += y;
        }
        wsum[t] = w;
    }
    __syncthreads();
    int incl = v + ((t >= 32) ? wsum[(t >> 5) - 1] : 0);
    if (t == 0) s_start = atomicAdd(&g_total, wsum[7]);
    __syncthreads();
    if (i < NN) {
        int off = s_start + incl - c;
        g_offsets[i] = off;
        g_cursor[i]  = off;
    }
}

// ---------------- scatter edges to CSR (src only) ----------------
__global__ void k_scatter(const void* __restrict__ ei) {
    int e = blockIdx.x * blockDim.x + threadIdx.x;
    if (e >= ETOT) return;
    int src, dst;
    if (e < EE) { src = edge_val(ei, e); dst = edge_val(ei, EE + e); }
    else        { src = e - EE; dst = e - EE; }
    int pos = atomicAdd(&g_cursor[dst], 1);
    g_csr_src[pos] = src;
}

// ---------------- layer1 aggregation: warp per node, batch-of-8 shared exp ----------------
__global__ void __launch_bounds__(256, 6) k_agg1(const float* __restrict__ b1) {
    int warp = (blockIdx.x * blockDim.x + threadIdx.x) >> 5;
    int l = threadIdx.x & 31;
    if (warp >= NN) return;
    int n = warp;
    int p0 = __ldg(&g_offsets[n]);
    int d  = __ldg(&g_counts[n]);
    int hsel = l >> 3;
    int el = l & 7;
    float adh = pick4(g_adst1[n], hsel);

    float acc[8] = {0,0,0,0,0,0,0,0};
    float denp = 0.f;                      // own-slot exp partial

    int base = 0;
    for (; base + 8 <= d; base += 8) {
        int s = g_csr_src[p0 + base + el];
        float ash = pick4(__ldg(&g_asrc1[s]), hsel);
        float ex = expf(lrelu(ash + adh));
        denp += ex;
#pragma unroll
        for (int j = 0; j < 8; j++) {
            int   src = __shfl_sync(FULLMASK, s,  hsel * 8 + j);
            float exh = __shfl_sync(FULLMASK, ex, hsel * 8 + j);
            uint4 u = g_h1h[src * 32 + l];
            __half2* hh = (__half2*)&u;
            float2 v0 = __half22float2(hh[0]);
            float2 v1 = __half22float2(hh[1]);
            float2 v2 = __half22float2(hh[2]);
            float2 v3 = __half22float2(hh[3]);
            acc[0] += exh * v0.x; acc[1] += exh * v0.y;
            acc[2] += exh * v1.x; acc[3] += exh * v1.y;
            acc[4] += exh * v2.x; acc[5] += exh * v2.y;
            acc[6] += exh * v3.x; acc[7] += exh * v3.y;
        }
    }
    if (base < d) {
        int jm = d - base;
        int s = 0; float ex = 0.f;
        if (el < jm) {
            s = g_csr_src[p0 + base + el];
            float ash = pick4(__ldg(&g_asrc1[s]), hsel);
            ex = expf(lrelu(ash + adh));
        }
        denp += ex;
        for (int j = 0; j < jm; j++) {
            int   src = __shfl_sync(FULLMASK, s,  hsel * 8 + j);
            float exh = __shfl_sync(FULLMASK, ex, hsel * 8 + j);
            uint4 u = g_h1h[src * 32 + l];
            __half2* hh = (__half2*)&u;
            float2 v0 = __half22float2(hh[0]);
            float2 v1 = __half22float2(hh[1]);
            float2 v2 = __half22float2(hh[2]);
            float2 v3 = __half22float2(hh[3]);
            acc[0] += exh * v0.x; acc[1] += exh * v0.y;
            acc[2] += exh * v1.x; acc[3] += exh * v1.y;
            acc[4] += exh * v2.x; acc[5] += exh * v2.y;
            acc[6] += exh * v3.x; acc[7] += exh * v3.y;
        }
    }

    float den = denp;
    den += __shfl_xor_sync(FULLMASK, den, 1);
    den += __shfl_xor_sync(FULLMASK, den, 2);
    den += __shfl_xor_sync(FULLMASK, den, 4);

    float inv = 0.25f / (den + 1e-16f);
    float r[8];
#pragma unroll
    for (int j = 0; j < 8; j++) {
        r[j] = acc[j] * inv;
        r[j] += __shfl_xor_sync(FULLMASK, r[j], 8);
        r[j] += __shfl_xor_sync(FULLMASK, r[j], 16);
    }
    if (l < 8) {
        float4 o0, o1;
        o0.x = elu(r[0] + b1[l * 8 + 0]);
        o0.y = elu(r[1] + b1[l * 8 + 1]);
        o0.z = elu(r[2] + b1[l * 8 + 2]);
        o0.w = elu(r[3] + b1[l * 8 + 3]);
        o1.x = elu(r[4] + b1[l * 8 + 4]);
        o1.y = elu(r[5] + b1[l * 8 + 5]);
        o1.z = elu(r[6] + b1[l * 8 + 6]);
        o1.w = elu(r[7] + b1[l * 8 + 7]);
        float4* op = (float4*)(g_h1out + n * 64) + l * 2;
        op[0] = o0;
        op[1] = o1;
    }
}

// ---------------- layer2 GEMM (64 nodes/block, 4x4 reg tile, fp16 out) + att coeffs ----------------
__global__ void k_gemm2(const float* __restrict__ W2) {
    __shared__ float Ws[4096];
    __shared__ float xs[4096];
    int t = threadIdx.x;
    int base = blockIdx.x * 64;
    for (int i = t; i < 4096; i += 256) {
        Ws[i] = W2[i];
        int gi = base * 64 + i;
        xs[i] = (gi < NN * 64) ? g_h1out[gi] : 0.f;
    }
    __syncthreads();
    int ct = t & 15, nt = t >> 4;
    float acc[4][4];
#pragma unroll
    for (int i = 0; i < 4; i++)
#pragma unroll
        for (int j = 0; j < 4; j++) acc[i][j] = 0.f;
#pragma unroll 8
    for (int k = 0; k < 64; k++) {
        float4 w = *(const float4*)&Ws[k * 64 + ct * 4];
#pragma unroll
        for (int i = 0; i < 4; i++) {
            float xv = xs[(nt * 4 + i) * 64 + k];
            acc[i][0] += xv * w.x; acc[i][1] += xv * w.y;
            acc[i][2] += xv * w.z; acc[i][3] += xv * w.w;
        }
    }
#pragma unroll
    for (int i = 0; i < 4; i++) {
        int node = base + nt * 4 + i;
        if (node < NN) {
            __half2 h0 = __floats2half2_rn(acc[i][0], acc[i][1]);
            __half2 h1 = __floats2half2_rn(acc[i][2], acc[i][3]);
            uint2 o;
            o.x = *(unsigned*)&h0;
            o.y = *(unsigned*)&h1;
            *(uint2*)&g_h2h[node * 32 + ct * 2] = o;
        }
    }
    if (t < 128) {
        int nl = t >> 1;
        bool isdst = t & 1;
        int node = base + nl;
        if (node < NN) {
            const float* u = g_u + 128 + (isdst ? 64 : 0);
            float a = 0.f;
#pragma unroll 16
            for (int k = 0; k < 64; k++) a += xs[nl * 64 + k] * u[k];
            if (isdst) g_adst2[node] = a; else g_asrc2[node] = a;
        }
    }
}

// ---------------- layer2 aggregation with inline exp, fp16 gathers; re-zeroes counts ------
__global__ void k_agg2(const float* __restrict__ b2, float* __restrict__ out) {
    int warp = (blockIdx.x * blockDim.x + threadIdx.x) >> 5;
    int l = threadIdx.x & 31;
    if (warp >= NN) return;
    int n = warp;
    int p0 = __ldg(&g_offsets[n]);
    int d  = __ldg(&g_counts[n]);
    float adst2n = g_adst2[n];

    int   sa0 = 0,  sa1 = 0;
    float ea0 = 0.f, ea1 = 0.f;
    if (l < d) {
        sa0 = g_csr_src[p0 + l];
        ea0 = expf(lrelu(g_asrc2[sa0] + adst2n));
    }
    if (l + 32 < d) {
        sa1 = g_csr_src[p0 + l + 32];
        ea1 = expf(lrelu(g_asrc2[sa1] + adst2n));
    }

    float a0 = 0.f, a1 = 0.f, den = 0.f;
    int dmain = d < 64 ? d : 64;
#pragma unroll 4
    for (int j = 0; j < dmain; j++) {
        int   src = __shfl_sync(FULLMASK, (j < 32) ? sa0 : sa1, j & 31);
        float ex  = __shfl_sync(FULLMASK, (j < 32) ? ea0 : ea1, j & 31);
        den += ex;
        unsigned hv = g_h2h[src * 32 + l];
        float2 v = __half22float2(*(__half2*)&hv);
        a0 += ex * v.x;
        a1 += ex * v.y;
    }
    for (int j = 64; j < d; j++) {
        int src = g_csr_src[p0 + j];
        float ex = expf(lrelu(g_asrc2[src] + adst2n));
        den += ex;
        unsigned hv = g_h2h[src * 32 + l];
        float2 v = __half22float2(*(__half2*)&hv);
        a0 += ex * v.x;
        a1 += ex * v.y;
    }
    float inv = 1.f / (den + 1e-16f);
    float2 o;
    o.x = elu(a0 * inv + b2[2 * l + 0]);
    o.y = elu(a1 * inv + b2[2 * l + 1]);
    ((float2*)(out + n * 64))[l] = o;
    if (l == 0) g_counts[n] = 0;           // ready for next graph replay
}

// ---------------- launch ----------------
extern "C" void kernel_launch(void* const* d_in, const int* in_sizes, int n_in,
                              void* d_out, int out_size) {
    const float* x   = (const float*)d_in[0];
    const void*  ei  = d_in[1];
    const float* W1  = (const float*)d_in[2];
    const float* as1 = (const float*)d_in[3];
    const float* ad1 = (const float*)d_in[4];
    const float* b1  = (const float*)d_in[5];
    const float* W2  = (const float*)d_in[6];
    const float* as2 = (const float*)d_in[7];
    const float* ad2 = (const float*)d_in[8];
    const float* b2  = (const float*)d_in[9];
    float* out = (float*)d_out;

    k_init<<<1, 128>>>((const unsigned int*)ei, W1, as1, ad1, W2, as2, ad2);
    k_gemm1_hist<<<G1B + (ETOT + 255) / 256, 256>>>(x, W1, ei);
    k_scan<<<NB, 256>>>();
    k_scatter<<<(ETOT + 255) / 256, 256>>>(ei);
    k_agg1<<<NN / 8, 256>>>(b1);
    k_gemm2<<<G1B, 256>>>(W2);
    k_agg2<<<NN / 8, 256>>>(b2, out);
}